// round 2
// baseline (speedup 1.0000x reference)
#include <cuda_runtime.h>
#include <cuda_bf16.h>

// Problem dims (fixed by the dataset)
#define NTOK   256
#define TOPK   2
#define NPAIRS 512          // NTOK * TOPK
#define HDIM   2048
#define IDIM   1024
#define NEXP   8

// ---------------- scratch (device globals; no allocation allowed) ----------
__device__ int   g_cnt[NEXP];
__device__ int   g_pairs[NEXP][NPAIRS];
__device__ float g_gu [NPAIRS * 2048];   // gate_up per pair  (4 MB)
__device__ float g_act[NPAIRS * 1024];   // silu(gate)*up     (2 MB)
__device__ float g_y  [NPAIRS * 2048];   // second GEMM out   (4 MB)

typedef unsigned long long ull;

__device__ __forceinline__ ull pack2(float a, float b) {
    ull r; asm("mov.b64 %0, {%1, %2};" : "=l"(r) : "f"(a), "f"(b)); return r;
}
__device__ __forceinline__ void fma2(ull &acc, ull a, ull b) {
    asm("fma.rn.f32x2 %0, %1, %2, %0;" : "+l"(acc) : "l"(a), "l"(b));
}
__device__ __forceinline__ float2 unpack2(ull v) {
    float2 r; asm("mov.b64 {%0, %1}, %2;" : "=f"(r.x), "=f"(r.y) : "l"(v)); return r;
}

// ---------------- routing: build per-expert pair lists ---------------------
// topk_ids: JAX requests int64 but with x64 disabled materializes INT32.
__global__ void route_kernel(const int* __restrict__ ids) {
    int tid = threadIdx.x;            // one thread per (token, slot) pair
    if (tid < NEXP) g_cnt[tid] = 0;
    __syncthreads();
    int e   = ids[tid] & 7;           // mask: wrong dtype degrades to wrong answer, not a crash
    int pos = atomicAdd(&g_cnt[e], 1);
    g_pairs[e][pos] = tid;            // pair id = t*TOPK + k
}

// ---------------- fused dequant-GEMM ---------------------------------------
// C[m, n] = sum_k A[row(m), k] * B[e, n, k] * S[e, n/128, k/128]
// ROWTOK=true : A = x (row = pair>>1, stride 2048), C = g_gu, KTOT = 2048
// ROWTOK=false: A = g_act (row = pair, stride 1024), C = g_y,  KTOT = 1024
// Tile 64x64x16, 256 threads, 4x4 micro-tile, packed f32x2 FMAs.
template<int KTOT, bool ROWTOK>
__global__ void __launch_bounds__(256) gemm_kernel(
    const float* __restrict__ Aext,
    const float* __restrict__ Ball,
    const float* __restrict__ Sall)
{
    const int e   = blockIdx.z;
    const int cnt = g_cnt[e];
    const int m0  = blockIdx.y << 6;
    if (m0 >= cnt) return;                       // uniform per block — safe
    const int n0  = blockIdx.x << 6;
    constexpr int KB = KTOT >> 7;                // k-blocks of 128

    const float* A = ROWTOK ? Aext : g_act;
    float*       C = ROWTOK ? g_gu : g_y;
    const int astride = ROWTOK ? 2048 : 1024;

    const float* B    = Ball + (size_t)e * 2048 * KTOT;
    const float* Srow = Sall + ((size_t)e * 16 + (n0 >> 7)) * KB;

    __shared__ ull   Ad[64][17];   // A value duplicated into both f32x2 lanes
    __shared__ float Bs[16][64];   // B (k-major) with scale folded in

    const int tid  = threadIdx.x;
    const int arow = tid >> 2, acol = (tid & 3) << 2;   // A: 64 rows x 16 k
    const int bn   = tid >> 2, bk   = (tid & 3) << 2;   // B: 64 n x 16 k

    // Gathered A row pointer (zero-pad rows beyond cnt)
    const float* Aptr = nullptr;
    {
        int mg = m0 + arow;
        if (mg < cnt) {
            int p = g_pairs[e][mg];
            int r = ROWTOK ? (p >> 1) : p;
            Aptr = A + (size_t)r * astride;
        }
    }
    const float* Bptr = B + (size_t)(n0 + bn) * KTOT + bk;

    const int tx = tid & 15, ty = tid >> 4;

    ull acc[4][2];
    const ull z = pack2(0.f, 0.f);
#pragma unroll
    for (int i = 0; i < 4; i++) { acc[i][0] = z; acc[i][1] = z; }

    // register-prefetch pipeline
    float4 av = Aptr ? *(const float4*)(Aptr + acol) : make_float4(0.f,0.f,0.f,0.f);
    float4 bv = *(const float4*)(Bptr);
    float  s  = Srow[0];

    for (int k0 = 0; k0 < KTOT; k0 += 16) {
        Ad[arow][acol + 0] = pack2(av.x, av.x);
        Ad[arow][acol + 1] = pack2(av.y, av.y);
        Ad[arow][acol + 2] = pack2(av.z, av.z);
        Ad[arow][acol + 3] = pack2(av.w, av.w);
        Bs[bk + 0][bn] = bv.x * s;
        Bs[bk + 1][bn] = bv.y * s;
        Bs[bk + 2][bn] = bv.z * s;
        Bs[bk + 3][bn] = bv.w * s;
        __syncthreads();

        int k1 = k0 + 16;
        if (k1 < KTOT) {   // prefetch next chunk; latency hidden by compute
            av = Aptr ? *(const float4*)(Aptr + k1 + acol) : make_float4(0.f,0.f,0.f,0.f);
            bv = *(const float4*)(Bptr + k1);
            s  = Srow[k1 >> 7];
        }

#pragma unroll
        for (int kk = 0; kk < 16; kk++) {
            ull b01 = *(const ull*)&Bs[kk][(tx << 2)];
            ull b23 = *(const ull*)&Bs[kk][(tx << 2) + 2];
#pragma unroll
            for (int i = 0; i < 4; i++) {
                ull a = Ad[(ty << 2) + i][kk];
                fma2(acc[i][0], a, b01);
                fma2(acc[i][1], a, b23);
            }
        }
        __syncthreads();
    }

#pragma unroll
    for (int i = 0; i < 4; i++) {
        int m = m0 + (ty << 2) + i;
        if (m < cnt) {
            int p = g_pairs[e][m];
            float2 v0 = unpack2(acc[i][0]);
            float2 v1 = unpack2(acc[i][1]);
            *(float4*)(C + (size_t)p * 2048 + n0 + (tx << 2)) =
                make_float4(v0.x, v0.y, v1.x, v1.y);
        }
    }
}

// ---------------- activation: silu(gate) * up -------------------------------
__global__ void act_kernel() {
    int idx = blockIdx.x * blockDim.x + threadIdx.x;   // NPAIRS * IDIM threads
    int p = idx >> 10;
    int i = idx & 1023;
    float g = g_gu[(size_t)p * 2048 + i];
    float u = g_gu[(size_t)p * 2048 + 1024 + i];
    g_act[idx] = (g / (1.f + expf(-g))) * u;
}

// ---------------- combine: out[t,h] = sum_k w[t,k] * y[t*2+k, h] -------------
__global__ void combine_kernel(const float* __restrict__ tw,
                               float* __restrict__ out) {
    int idx = blockIdx.x * blockDim.x + threadIdx.x;   // NTOK * HDIM threads
    int t = idx >> 11;
    int h = idx & 2047;
    out[idx] = tw[2 * t + 0] * g_y[(size_t)(2 * t + 0) * 2048 + h]
             + tw[2 * t + 1] * g_y[(size_t)(2 * t + 1) * 2048 + h];
}

// ---------------- entry ------------------------------------------------------
extern "C" void kernel_launch(void* const* d_in, const int* in_sizes, int n_in,
                              void* d_out, int out_size) {
    const float* x   = (const float*)d_in[0];
    const int*   ids = (const int*)d_in[1];     // int32 (JAX x64 disabled)
    const float* tw  = (const float*)d_in[2];
    const float* w13 = (const float*)d_in[3];
    const float* s13 = (const float*)d_in[4];
    const float* w2  = (const float*)d_in[5];
    const float* s2  = (const float*)d_in[6];
    float* out = (float*)d_out;

    route_kernel<<<1, NPAIRS>>>(ids);

    // GEMM1: [512 pairs x 2048(H)] @ w13[e]^T -> gu [512 x 2048(2I)]
    dim3 grid1(2048 / 64, NPAIRS / 64, NEXP);
    gemm_kernel<2048, true><<<grid1, 256>>>(x, w13, s13);

    act_kernel<<<(NPAIRS * IDIM) / 256, 256>>>();

    // GEMM2: act [512 x 1024(I)] @ w2[e]^T -> y [512 x 2048(H)]
    dim3 grid2(2048 / 64, NPAIRS / 64, NEXP);
    gemm_kernel<1024, false><<<grid2, 256>>>(nullptr, w2, s2);

    combine_kernel<<<(NTOK * HDIM) / 256, 256>>>(tw, out);
}

// round 4
// speedup vs baseline: 3.0300x; 3.0300x over previous
#include <cuda_runtime.h>
#include <cstdint>

#define NTOK   256
#define TOPK   2
#define NPAIRS 512
#define NEXP   8

// ---------------- scratch (device globals) ----------------------------------
__device__ int   g_cnt[NEXP];
__device__ int   g_pairs[NEXP][NPAIRS];
__device__ int   g_pos[NPAIRS];
__device__ float g_Apad[NEXP * 512 * 2048];   // gathered x rows, tf32, zero-padded
__device__ float g_guE [NEXP * 512 * 2048];   // gate_up, expert-ordered
__device__ float g_actE[NEXP * 512 * 1024];   // silu(gate)*up, tf32
__device__ float g_yE  [NEXP * 512 * 2048];   // GEMM2 out

// ---------------- helpers ----------------------------------------------------
__device__ __forceinline__ uint32_t smem_u32(const void* p) {
    uint32_t a;
    asm("{ .reg .u64 t; cvta.to.shared.u64 t, %1; cvt.u32.u64 %0, t; }" : "=r"(a) : "l"(p));
    return a;
}
__device__ __forceinline__ uint32_t f2tf32(float x) {
    uint32_t u; asm("cvt.rna.tf32.f32 %0, %1;" : "=r"(u) : "f"(x)); return u;
}
__device__ __forceinline__ float f2tf32f(float x) { return __uint_as_float(f2tf32(x)); }

__device__ __forceinline__ void cpa16(uint32_t dst, const void* src) {
    asm volatile("cp.async.cg.shared.global [%0], [%1], 16;" :: "r"(dst), "l"(src));
}
#define CP_COMMIT() asm volatile("cp.async.commit_group;" ::: "memory")
#define CP_WAIT0()  asm volatile("cp.async.wait_group 0;" ::: "memory")

__device__ __forceinline__ void sts128(uint32_t a, uint32_t x, uint32_t y, uint32_t z, uint32_t w) {
    asm volatile("st.shared.v4.b32 [%0], {%1, %2, %3, %4};" :: "r"(a), "r"(x), "r"(y), "r"(z), "r"(w) : "memory");
}
__device__ __forceinline__ void ldsm4(uint32_t& r0, uint32_t& r1, uint32_t& r2, uint32_t& r3, uint32_t a) {
    asm volatile("ldmatrix.sync.aligned.m8n8.x4.shared.b16 {%0,%1,%2,%3}, [%4];"
                 : "=r"(r0), "=r"(r1), "=r"(r2), "=r"(r3) : "r"(a));
}
__device__ __forceinline__ void ldsm2(uint32_t& r0, uint32_t& r1, uint32_t a) {
    asm volatile("ldmatrix.sync.aligned.m8n8.x2.shared.b16 {%0,%1}, [%2];"
                 : "=r"(r0), "=r"(r1) : "r"(a));
}
__device__ __forceinline__ void mma8(float* c, const uint32_t* a, const uint32_t* b) {
    asm volatile("mma.sync.aligned.m16n8k8.row.col.f32.tf32.tf32.f32 "
                 "{%0,%1,%2,%3}, {%4,%5,%6,%7}, {%8,%9}, {%0,%1,%2,%3};"
                 : "+f"(c[0]), "+f"(c[1]), "+f"(c[2]), "+f"(c[3])
                 : "r"(a[0]), "r"(a[1]), "r"(a[2]), "r"(a[3]), "r"(b[0]), "r"(b[1]));
}

// ---------------- routing ----------------------------------------------------
__global__ void route_kernel(const int* __restrict__ ids) {
    int tid = threadIdx.x;
    if (tid < NEXP) g_cnt[tid] = 0;
    __syncthreads();
    int e   = ids[tid] & 7;
    int pos = atomicAdd(&g_cnt[e], 1);
    g_pairs[e][pos] = tid;
    g_pos[tid] = e * 512 + pos;
}

// ---------------- gather x rows into padded, tf32-converted A ----------------
__global__ void gather_kernel(const float* __restrict__ x) {
    int bid = blockIdx.x;               // 4096 blocks: (e, m)
    int e = bid >> 9, m = bid & 511;
    int cnt = g_cnt[e];
    int lim = (cnt + 127) & ~127;
    if (m >= lim) return;
    float4* dst = (float4*)(g_Apad + ((size_t)e * 512 + m) * 2048);
    if (m < cnt) {
        int p = g_pairs[e][m];
        const float4* src = (const float4*)(x + (size_t)(p >> 1) * 2048);
#pragma unroll
        for (int i = 0; i < 2; i++) {
            float4 v = src[threadIdx.x + 256 * i];
            dst[threadIdx.x + 256 * i] = make_float4(f2tf32f(v.x), f2tf32f(v.y),
                                                     f2tf32f(v.z), f2tf32f(v.w));
        }
    } else {
#pragma unroll
        for (int i = 0; i < 2; i++)
            dst[threadIdx.x + 256 * i] = make_float4(0.f, 0.f, 0.f, 0.f);
    }
}

// ---------------- tf32 mma.sync GEMM ------------------------------------------
// C[e,m,n] = sum_k A[e,m,k] * B[e,n,k] * S[e, n/128, k/128]
// BM=128, BN=128, BK=32; 256 threads; warps 2(m) x 4(n), warp tile 64x32.
// SMEM rows padded to 36 floats (144B) -> conflict-free ldmatrix.
#define STG_F 4608                      // 128*36 floats per stage per matrix

template<int KTOT, bool G1>
__global__ void __launch_bounds__(256) mma_gemm(
    const float* __restrict__ Ball,
    const float* __restrict__ Sall)
{
    constexpr int KS = KTOT / 32;
    constexpr int KB = KTOT / 128;

    const int e   = blockIdx.z;
    const int cnt = g_cnt[e];
    const int m0  = blockIdx.y << 7;
    if (m0 >= cnt) return;
    const int n0  = blockIdx.x << 7;

    const float* Aall = G1 ? g_Apad : g_actE;
    float*       Call = G1 ? g_guE  : g_yE;

    extern __shared__ float dsm[];
    const uint32_t sbase = smem_u32(dsm);
    // layout: A stage0, A stage1, B stage0, B stage1 (each STG_F floats)

    const int tid  = threadIdx.x;
    const int lane = tid & 31, w = tid >> 5;
    const int warpM = (w & 1) << 6;     // 0 or 64
    const int warpN = (w >> 1) << 5;    // 0,32,64,96

    const float* Ag = Aall + ((size_t)e * 512 + m0) * KTOT;
    const float4* Bg4 = (const float4*)(Ball + ((size_t)e * 2048 + n0) * KTOT);
    const float* Srow = Sall + ((size_t)e * 16 + (n0 >> 7)) * KB;
    const int kq4 = KTOT / 4;

    // loader mapping: q = tid + 256*i -> row = q>>3 (0..127), c16 = q&7
    const int lrow = tid >> 3, lcol = tid & 7;
    const uint32_t ldst = (uint32_t)(lrow * 144 + lcol * 16);

    // ldmatrix per-lane address bases
    const int l2 = lane & 15;
    const uint32_t aFragBase = (uint32_t)((warpM + (lane & 7) + ((lane >> 3) & 1) * 8) * 144
                                          + (lane >> 4) * 16);
    const uint32_t bFragBase = (uint32_t)((warpN + (l2 & 7)) * 144 + ((l2 >> 3) & 1) * 16);

    float acc[4][4][4];
#pragma unroll
    for (int mt = 0; mt < 4; mt++)
#pragma unroll
        for (int nt = 0; nt < 4; nt++)
#pragma unroll
            for (int i = 0; i < 4; i++) acc[mt][nt][i] = 0.f;

    // -------- prologue: fill stage 0 --------
    {
        const float sc = Srow[0];
#pragma unroll
        for (int i = 0; i < 4; i++) {
            int row = lrow + 32 * i;
            uint32_t d = ldst + (uint32_t)(32 * i * 144);
            cpa16(sbase + d, Ag + (size_t)row * KTOT + lcol * 4);
            float4 b = Bg4[(size_t)row * kq4 + lcol];
            sts128(sbase + 2 * STG_F * 4 + d,
                   f2tf32(b.x * sc), f2tf32(b.y * sc), f2tf32(b.z * sc), f2tf32(b.w * sc));
        }
        CP_COMMIT();
        CP_WAIT0();
        __syncthreads();
    }

    // -------- main loop --------
    for (int ks = 0; ks < KS; ks++) {
        const int cur = ks & 1, nxt = cur ^ 1;
        const uint32_t aCur = sbase + (uint32_t)(cur * STG_F * 4);
        const uint32_t bCur = sbase + (uint32_t)((2 * STG_F + cur * STG_F) * 4);

        float4 bst[4];
        float  scn = 0.f;
        const bool more = (ks + 1 < KS);
        if (more) {
            const int kf = (ks + 1) * 32;
            scn = Srow[(ks + 1) >> 2];
            const uint32_t aNxt = sbase + (uint32_t)(nxt * STG_F * 4);
#pragma unroll
            for (int i = 0; i < 4; i++) {
                int row = lrow + 32 * i;
                cpa16(aNxt + ldst + (uint32_t)(32 * i * 144),
                      Ag + (size_t)row * KTOT + kf + lcol * 4);
                bst[i] = Bg4[(size_t)row * kq4 + (kf >> 2) + lcol];
            }
            CP_COMMIT();
        }

        // compute on cur
#pragma unroll
        for (int s = 0; s < 4; s++) {
            uint32_t af[4][4], bf[4][2];
#pragma unroll
            for (int mt = 0; mt < 4; mt++)
                ldsm4(af[mt][0], af[mt][1], af[mt][2], af[mt][3],
                      aCur + aFragBase + (uint32_t)(mt * 16 * 144 + s * 32));
#pragma unroll
            for (int nt = 0; nt < 4; nt++)
                ldsm2(bf[nt][0], bf[nt][1],
                      bCur + bFragBase + (uint32_t)(nt * 8 * 144 + s * 32));
#pragma unroll
            for (int mt = 0; mt < 4; mt++)
#pragma unroll
                for (int nt = 0; nt < 4; nt++)
                    mma8(acc[mt][nt], af[mt], bf[nt]);
        }

        if (more) {
            const uint32_t bNxt = sbase + (uint32_t)((2 * STG_F + nxt * STG_F) * 4);
#pragma unroll
            for (int i = 0; i < 4; i++) {
                sts128(bNxt + ldst + (uint32_t)(32 * i * 144),
                       f2tf32(bst[i].x * scn), f2tf32(bst[i].y * scn),
                       f2tf32(bst[i].z * scn), f2tf32(bst[i].w * scn));
            }
            CP_WAIT0();
        }
        __syncthreads();
    }

    // -------- epilogue: regs -> global --------
    float* Cb = Call + ((size_t)e * 512 + m0) * 2048 + n0;
    const int rr = lane >> 2, cc = (lane & 3) << 1;
#pragma unroll
    for (int mt = 0; mt < 4; mt++) {
#pragma unroll
        for (int nt = 0; nt < 4; nt++) {
            float* p0 = Cb + (size_t)(warpM + mt * 16 + rr) * 2048 + warpN + nt * 8 + cc;
            *(float2*)p0 = make_float2(acc[mt][nt][0], acc[mt][nt][1]);
            *(float2*)(p0 + 8 * 2048) = make_float2(acc[mt][nt][2], acc[mt][nt][3]);
        }
    }
}

// ---------------- activation ---------------------------------------------------
__global__ void act_kernel() {
    int idx = blockIdx.x * 256 + threadIdx.x;     // over 8*512*1024/4
    int row = idx >> 8;
    int e = row >> 9, m = row & 511;
    int lim = (g_cnt[e] + 127) & ~127;
    if (m >= lim) return;
    int i4 = (idx & 255) << 2;
    const float* gu = g_guE + (size_t)row * 2048;
    float4 g = *(const float4*)(gu + i4);
    float4 u = *(const float4*)(gu + 1024 + i4);
    float4 a;
    a.x = f2tf32f((g.x / (1.f + expf(-g.x))) * u.x);
    a.y = f2tf32f((g.y / (1.f + expf(-g.y))) * u.y);
    a.z = f2tf32f((g.z / (1.f + expf(-g.z))) * u.z);
    a.w = f2tf32f((g.w / (1.f + expf(-g.w))) * u.w);
    *(float4*)(g_actE + (size_t)row * 1024 + i4) = a;
}

// ---------------- combine -------------------------------------------------------
__global__ void combine_kernel(const float* __restrict__ tw,
                               float* __restrict__ out) {
    int idx = blockIdx.x * 256 + threadIdx.x;     // over 256*2048/4
    int t  = idx >> 9;
    int h4 = (idx & 511) << 2;
    float w0 = tw[2 * t + 0], w1 = tw[2 * t + 1];
    const float4* y0 = (const float4*)(g_yE + (size_t)g_pos[2 * t + 0] * 2048 + h4);
    const float4* y1 = (const float4*)(g_yE + (size_t)g_pos[2 * t + 1] * 2048 + h4);
    float4 a = *y0, b = *y1;
    *(float4*)(out + (size_t)t * 2048 + h4) = make_float4(
        w0 * a.x + w1 * b.x, w0 * a.y + w1 * b.y,
        w0 * a.z + w1 * b.z, w0 * a.w + w1 * b.w);
}

// ---------------- entry ---------------------------------------------------------
extern "C" void kernel_launch(void* const* d_in, const int* in_sizes, int n_in,
                              void* d_out, int out_size) {
    const float* x   = (const float*)d_in[0];
    const int*   ids = (const int*)d_in[1];
    const float* tw  = (const float*)d_in[2];
    const float* w13 = (const float*)d_in[3];
    const float* s13 = (const float*)d_in[4];
    const float* w2  = (const float*)d_in[5];
    const float* s2  = (const float*)d_in[6];
    float* out = (float*)d_out;

    const int SMEM_DYN = 4 * STG_F * 4;   // 73728 bytes: A0,A1,B0,B1
    cudaFuncSetAttribute(mma_gemm<2048, true>,  cudaFuncAttributeMaxDynamicSharedMemorySize, SMEM_DYN);
    cudaFuncSetAttribute(mma_gemm<1024, false>, cudaFuncAttributeMaxDynamicSharedMemorySize, SMEM_DYN);

    route_kernel<<<1, NPAIRS>>>(ids);
    gather_kernel<<<NEXP * 512, 256>>>(x);

    dim3 grid(16, 4, NEXP);
    mma_gemm<2048, true><<<grid, 256, SMEM_DYN>>>(w13, s13);

    act_kernel<<<(NEXP * 512 * 1024 / 4) / 256, 256>>>();

    mma_gemm<1024, false><<<grid, 256, SMEM_DYN>>>(w2, s2);

    combine_kernel<<<(NTOK * 2048 / 4) / 256, 256>>>(tw, out);
}

// round 5
// speedup vs baseline: 4.1269x; 1.3620x over previous
#include <cuda_runtime.h>
#include <cstdint>

#define NTOK   256
#define TOPK   2
#define NPAIRS 512
#define NEXP   8

// ---------------- scratch (device globals) ----------------------------------
__device__ int   g_cnt[NEXP];
__device__ int   g_pairs[NEXP][NPAIRS];
__device__ int   g_pos[NPAIRS];
__device__ float g_Apad[NEXP * 512 * 2048];   // gathered x rows, tf32, zero-padded
__device__ float g_guE [NEXP * 512 * 2048];   // gate_up, expert-ordered
__device__ float g_actE[NEXP * 512 * 1024];   // silu(gate)*up, tf32
__device__ float g_yE  [NEXP * 512 * 2048];   // GEMM2 out

// ---------------- helpers ----------------------------------------------------
__device__ __forceinline__ uint32_t smem_u32(const void* p) {
    uint32_t a;
    asm("{ .reg .u64 t; cvta.to.shared.u64 t, %1; cvt.u32.u64 %0, t; }" : "=r"(a) : "l"(p));
    return a;
}
__device__ __forceinline__ uint32_t f2tf32(float x) {
    uint32_t u; asm("cvt.rna.tf32.f32 %0, %1;" : "=r"(u) : "f"(x)); return u;
}
__device__ __forceinline__ float f2tf32f(float x) { return __uint_as_float(f2tf32(x)); }

__device__ __forceinline__ void cpa16(uint32_t dst, const void* src) {
    asm volatile("cp.async.cg.shared.global [%0], [%1], 16;" :: "r"(dst), "l"(src));
}
#define CP_COMMIT() asm volatile("cp.async.commit_group;" ::: "memory")
#define CP_WAIT0()  asm volatile("cp.async.wait_group 0;" ::: "memory")

__device__ __forceinline__ void sts128(uint32_t a, uint32_t x, uint32_t y, uint32_t z, uint32_t w) {
    asm volatile("st.shared.v4.b32 [%0], {%1, %2, %3, %4};" :: "r"(a), "r"(x), "r"(y), "r"(z), "r"(w) : "memory");
}
__device__ __forceinline__ void ldsm4(uint32_t& r0, uint32_t& r1, uint32_t& r2, uint32_t& r3, uint32_t a) {
    asm volatile("ldmatrix.sync.aligned.m8n8.x4.shared.b16 {%0,%1,%2,%3}, [%4];"
                 : "=r"(r0), "=r"(r1), "=r"(r2), "=r"(r3) : "r"(a));
}
__device__ __forceinline__ void ldsm2(uint32_t& r0, uint32_t& r1, uint32_t a) {
    asm volatile("ldmatrix.sync.aligned.m8n8.x2.shared.b16 {%0,%1}, [%2];"
                 : "=r"(r0), "=r"(r1) : "r"(a));
}
__device__ __forceinline__ void mma8(float* c, const uint32_t* a, const uint32_t* b) {
    asm volatile("mma.sync.aligned.m16n8k8.row.col.f32.tf32.tf32.f32 "
                 "{%0,%1,%2,%3}, {%4,%5,%6,%7}, {%8,%9}, {%0,%1,%2,%3};"
                 : "+f"(c[0]), "+f"(c[1]), "+f"(c[2]), "+f"(c[3])
                 : "r"(a[0]), "r"(a[1]), "r"(a[2]), "r"(a[3]), "r"(b[0]), "r"(b[1]));
}

// ---------------- routing ----------------------------------------------------
__global__ void route_kernel(const int* __restrict__ ids) {
    int tid = threadIdx.x;
    if (tid < NEXP) g_cnt[tid] = 0;
    __syncthreads();
    int e   = ids[tid] & 7;
    int pos = atomicAdd(&g_cnt[e], 1);
    g_pairs[e][pos] = tid;
    g_pos[tid] = e * 512 + pos;
}

// ---------------- gather x rows into padded, tf32-converted A ----------------
__global__ void gather_kernel(const float* __restrict__ x) {
    int bid = blockIdx.x;               // 4096 blocks: (e, m)
    int e = bid >> 9, m = bid & 511;
    int cnt = g_cnt[e];
    int lim = (cnt + 63) & ~63;
    if (m >= lim) return;
    float4* dst = (float4*)(g_Apad + ((size_t)e * 512 + m) * 2048);
    if (m < cnt) {
        int p = g_pairs[e][m];
        const float4* src = (const float4*)(x + (size_t)(p >> 1) * 2048);
#pragma unroll
        for (int i = 0; i < 2; i++) {
            float4 v = src[threadIdx.x + 256 * i];
            dst[threadIdx.x + 256 * i] = make_float4(f2tf32f(v.x), f2tf32f(v.y),
                                                     f2tf32f(v.z), f2tf32f(v.w));
        }
    } else {
#pragma unroll
        for (int i = 0; i < 2; i++)
            dst[threadIdx.x + 256 * i] = make_float4(0.f, 0.f, 0.f, 0.f);
    }
}

// ---------------- tf32 mma.sync GEMM ------------------------------------------
// C[e,m,n] = sum_k A[e,m,k] * B[e,n,k] * S[e, n/128, k/128]
// BM=64, BN=128, BK=32; 256 threads; warps 2(m) x 4(n), warp tile 32x32.
// SMEM rows padded to 36 floats (144B) -> conflict-free ldmatrix.
// 2 CTAs/SM (regs ~90, smem 55.3KB).
#define A_STG 2304                      // 64*36 floats per A stage
#define B_STG 4608                      // 128*36 floats per B stage

template<int KTOT, bool G1>
__global__ void __launch_bounds__(256, 2) mma_gemm(
    const float* __restrict__ Ball,
    const float* __restrict__ Sall)
{
    constexpr int KS = KTOT / 32;
    constexpr int KB = KTOT / 128;

    const int e   = blockIdx.z;
    const int cnt = g_cnt[e];
    const int m0  = blockIdx.y << 6;
    if (m0 >= cnt) return;
    const int n0  = blockIdx.x << 7;

    const float* Aall = G1 ? g_Apad : g_actE;
    float*       Call = G1 ? g_guE  : g_yE;

    extern __shared__ float dsm[];
    const uint32_t sbase = smem_u32(dsm);
    // layout: A0, A1, B0, B1

    const int tid  = threadIdx.x;
    const int lane = tid & 31, w = tid >> 5;
    const int warpM = (w & 1) << 5;     // 0 or 32
    const int warpN = (w >> 1) << 5;    // 0,32,64,96

    const float* Ag = Aall + ((size_t)e * 512 + m0) * KTOT;
    const float4* Bg4 = (const float4*)(Ball + ((size_t)e * 2048 + n0) * KTOT);
    const float* Srow = Sall + ((size_t)e * 16 + (n0 >> 7)) * KB;
    const int kq4 = KTOT / 4;

    // loader mappings (16B granules, 8 per 32-float row chunk)
    const int lrow = tid >> 3, lcol = tid & 7;          // B: 4 rows strided 32; A: 2 rows strided 32
    const uint32_t ldst = (uint32_t)(lrow * 144 + lcol * 16);

    // ldmatrix per-lane address bases
    const int l2 = lane & 15;
    const uint32_t aFragBase = (uint32_t)((warpM + (lane & 7) + ((lane >> 3) & 1) * 8) * 144
                                          + (lane >> 4) * 16);
    const uint32_t bFragBase = (uint32_t)((warpN + (l2 & 7)) * 144 + ((l2 >> 3) & 1) * 16);

    float acc[2][4][4];
#pragma unroll
    for (int mt = 0; mt < 2; mt++)
#pragma unroll
        for (int nt = 0; nt < 4; nt++)
#pragma unroll
            for (int i = 0; i < 4; i++) acc[mt][nt][i] = 0.f;

    // -------- prologue: fill stage 0 --------
    {
        const float sc = Srow[0];
#pragma unroll
        for (int i = 0; i < 2; i++) {   // A: 64 rows
            cpa16(sbase + ldst + (uint32_t)(32 * i * 144),
                  Ag + (size_t)(lrow + 32 * i) * KTOT + lcol * 4);
        }
#pragma unroll
        for (int i = 0; i < 4; i++) {   // B: 128 rows
            float4 b = Bg4[(size_t)(lrow + 32 * i) * kq4 + lcol];
            sts128(sbase + 2 * A_STG * 4 + ldst + (uint32_t)(32 * i * 144),
                   f2tf32(b.x * sc), f2tf32(b.y * sc), f2tf32(b.z * sc), f2tf32(b.w * sc));
        }
        CP_COMMIT();
        CP_WAIT0();
        __syncthreads();
    }

    // -------- main loop --------
    for (int ks = 0; ks < KS; ks++) {
        const int cur = ks & 1, nxt = cur ^ 1;
        const uint32_t aCur = sbase + (uint32_t)(cur * A_STG * 4);
        const uint32_t bCur = sbase + (uint32_t)((2 * A_STG + cur * B_STG) * 4);

        float4 bst[4];
        float  scn = 0.f;
        const bool more = (ks + 1 < KS);
        if (more) {
            const int kf = (ks + 1) * 32;
            scn = Srow[(ks + 1) >> 2];
            const uint32_t aNxt = sbase + (uint32_t)(nxt * A_STG * 4);
#pragma unroll
            for (int i = 0; i < 2; i++)
                cpa16(aNxt + ldst + (uint32_t)(32 * i * 144),
                      Ag + (size_t)(lrow + 32 * i) * KTOT + kf + lcol * 4);
#pragma unroll
            for (int i = 0; i < 4; i++)
                bst[i] = Bg4[(size_t)(lrow + 32 * i) * kq4 + (kf >> 2) + lcol];
            CP_COMMIT();
        }

        // compute on cur
#pragma unroll
        for (int s = 0; s < 4; s++) {
            uint32_t af[2][4], bf[4][2];
#pragma unroll
            for (int mt = 0; mt < 2; mt++)
                ldsm4(af[mt][0], af[mt][1], af[mt][2], af[mt][3],
                      aCur + aFragBase + (uint32_t)(mt * 16 * 144 + s * 32));
#pragma unroll
            for (int nt = 0; nt < 4; nt++)
                ldsm2(bf[nt][0], bf[nt][1],
                      bCur + bFragBase + (uint32_t)(nt * 8 * 144 + s * 32));
#pragma unroll
            for (int mt = 0; mt < 2; mt++)
#pragma unroll
                for (int nt = 0; nt < 4; nt++)
                    mma8(acc[mt][nt], af[mt], bf[nt]);
        }

        if (more) {
            const uint32_t bNxt = sbase + (uint32_t)((2 * A_STG + nxt * B_STG) * 4);
#pragma unroll
            for (int i = 0; i < 4; i++) {
                sts128(bNxt + ldst + (uint32_t)(32 * i * 144),
                       f2tf32(bst[i].x * scn), f2tf32(bst[i].y * scn),
                       f2tf32(bst[i].z * scn), f2tf32(bst[i].w * scn));
            }
            CP_WAIT0();
        }
        __syncthreads();
    }

    // -------- epilogue: regs -> global --------
    float* Cb = Call + ((size_t)e * 512 + m0) * 2048 + n0;
    const int rr = lane >> 2, cc = (lane & 3) << 1;
#pragma unroll
    for (int mt = 0; mt < 2; mt++) {
#pragma unroll
        for (int nt = 0; nt < 4; nt++) {
            float* p0 = Cb + (size_t)(warpM + mt * 16 + rr) * 2048 + warpN + nt * 8 + cc;
            *(float2*)p0 = make_float2(acc[mt][nt][0], acc[mt][nt][1]);
            *(float2*)(p0 + 8 * 2048) = make_float2(acc[mt][nt][2], acc[mt][nt][3]);
        }
    }
}

// ---------------- activation ---------------------------------------------------
__global__ void act_kernel() {
    int idx = blockIdx.x * 256 + threadIdx.x;     // over 8*512*1024/4
    int row = idx >> 8;
    int e = row >> 9, m = row & 511;
    int lim = (g_cnt[e] + 63) & ~63;
    if (m >= lim) return;
    int i4 = (idx & 255) << 2;
    const float* gu = g_guE + (size_t)row * 2048;
    float4 g = *(const float4*)(gu + i4);
    float4 u = *(const float4*)(gu + 1024 + i4);
    float4 a;
    a.x = f2tf32f((g.x / (1.f + expf(-g.x))) * u.x);
    a.y = f2tf32f((g.y / (1.f + expf(-g.y))) * u.y);
    a.z = f2tf32f((g.z / (1.f + expf(-g.z))) * u.z);
    a.w = f2tf32f((g.w / (1.f + expf(-g.w))) * u.w);
    *(float4*)(g_actE + (size_t)row * 1024 + i4) = a;
}

// ---------------- combine -------------------------------------------------------
__global__ void combine_kernel(const float* __restrict__ tw,
                               float* __restrict__ out) {
    int idx = blockIdx.x * 256 + threadIdx.x;     // over 256*2048/4
    int t  = idx >> 9;
    int h4 = (idx & 511) << 2;
    float w0 = tw[2 * t + 0], w1 = tw[2 * t + 1];
    const float4* y0 = (const float4*)(g_yE + (size_t)g_pos[2 * t + 0] * 2048 + h4);
    const float4* y1 = (const float4*)(g_yE + (size_t)g_pos[2 * t + 1] * 2048 + h4);
    float4 a = *y0, b = *y1;
    *(float4*)(out + (size_t)t * 2048 + h4) = make_float4(
        w0 * a.x + w1 * b.x, w0 * a.y + w1 * b.y,
        w0 * a.z + w1 * b.z, w0 * a.w + w1 * b.w);
}

// ---------------- entry ---------------------------------------------------------
extern "C" void kernel_launch(void* const* d_in, const int* in_sizes, int n_in,
                              void* d_out, int out_size) {
    const float* x   = (const float*)d_in[0];
    const int*   ids = (const int*)d_in[1];
    const float* tw  = (const float*)d_in[2];
    const float* w13 = (const float*)d_in[3];
    const float* s13 = (const float*)d_in[4];
    const float* w2  = (const float*)d_in[5];
    const float* s2  = (const float*)d_in[6];
    float* out = (float*)d_out;

    const int SMEM_DYN = (2 * A_STG + 2 * B_STG) * 4;   // 55296 bytes
    cudaFuncSetAttribute(mma_gemm<2048, true>,  cudaFuncAttributeMaxDynamicSharedMemorySize, SMEM_DYN);
    cudaFuncSetAttribute(mma_gemm<1024, false>, cudaFuncAttributeMaxDynamicSharedMemorySize, SMEM_DYN);

    route_kernel<<<1, NPAIRS>>>(ids);
    gather_kernel<<<NEXP * 512, 256>>>(x);

    dim3 grid(16, 8, NEXP);
    mma_gemm<2048, true><<<grid, 256, SMEM_DYN>>>(w13, s13);

    act_kernel<<<(NEXP * 512 * 1024 / 4) / 256, 256>>>();

    mma_gemm<1024, false><<<grid, 256, SMEM_DYN>>>(w2, s2);

    combine_kernel<<<(NTOK * 2048 / 4) / 256, 256>>>(tw, out);
}

// round 6
// speedup vs baseline: 5.5779x; 1.3516x over previous
#include <cuda_runtime.h>
#include <cuda_fp16.h>
#include <cstdint>

#define NTOK   256
#define NPAIRS 512
#define NEXP   8

// ---------------- scratch (device globals) ----------------------------------
__device__ int    g_cnt[NEXP];
__device__ int    g_pairs[NEXP][NPAIRS];
__device__ int    g_pos[NPAIRS];
__device__ __half g_Ah  [NEXP * 512 * 2048];   // gathered x rows, fp16, zero-padded
__device__ __half g_actE[NEXP * 512 * 1024];   // silu(gate)*up, fp16
__device__ float  g_yE  [NEXP * 512 * 2048];   // GEMM2 out

// ---------------- helpers ----------------------------------------------------
__device__ __forceinline__ uint32_t smem_u32(const void* p) {
    uint32_t a;
    asm("{ .reg .u64 t; cvta.to.shared.u64 t, %1; cvt.u32.u64 %0, t; }" : "=r"(a) : "l"(p));
    return a;
}
__device__ __forceinline__ uint32_t pack_h2(float lo, float hi) {
    uint32_t r;
    asm("cvt.rn.f16x2.f32 %0, %1, %2;" : "=r"(r) : "f"(hi), "f"(lo));
    return r;
}
__device__ __forceinline__ void cpa16(uint32_t dst, const void* src) {
    asm volatile("cp.async.cg.shared.global [%0], [%1], 16;" :: "r"(dst), "l"(src));
}
#define CP_COMMIT() asm volatile("cp.async.commit_group;" ::: "memory")
#define CP_WAIT0()  asm volatile("cp.async.wait_group 0;" ::: "memory")

__device__ __forceinline__ void sts128(uint32_t a, uint32_t x, uint32_t y, uint32_t z, uint32_t w) {
    asm volatile("st.shared.v4.b32 [%0], {%1, %2, %3, %4};" :: "r"(a), "r"(x), "r"(y), "r"(z), "r"(w) : "memory");
}
__device__ __forceinline__ void ldsm4(uint32_t& r0, uint32_t& r1, uint32_t& r2, uint32_t& r3, uint32_t a) {
    asm volatile("ldmatrix.sync.aligned.m8n8.x4.shared.b16 {%0,%1,%2,%3}, [%4];"
                 : "=r"(r0), "=r"(r1), "=r"(r2), "=r"(r3) : "r"(a));
}
__device__ __forceinline__ void ldsm2(uint32_t& r0, uint32_t& r1, uint32_t a) {
    asm volatile("ldmatrix.sync.aligned.m8n8.x2.shared.b16 {%0,%1}, [%2];"
                 : "=r"(r0), "=r"(r1) : "r"(a));
}
__device__ __forceinline__ void mma16(float* c, const uint32_t* a, const uint32_t* b) {
    asm volatile("mma.sync.aligned.m16n8k16.row.col.f32.f16.f16.f32 "
                 "{%0,%1,%2,%3}, {%4,%5,%6,%7}, {%8,%9}, {%0,%1,%2,%3};"
                 : "+f"(c[0]), "+f"(c[1]), "+f"(c[2]), "+f"(c[3])
                 : "r"(a[0]), "r"(a[1]), "r"(a[2]), "r"(a[3]), "r"(b[0]), "r"(b[1]));
}

// ---------------- routing ----------------------------------------------------
__global__ void route_kernel(const int* __restrict__ ids) {
    int tid = threadIdx.x;
    if (tid < NEXP) g_cnt[tid] = 0;
    __syncthreads();
    int e   = ids[tid] & 7;
    int pos = atomicAdd(&g_cnt[e], 1);
    g_pairs[e][pos] = tid;
    g_pos[tid] = e * 512 + pos;
}

// ---------------- gather x rows into padded fp16 A ----------------------------
__global__ void gather_kernel(const float* __restrict__ x) {
    int bid = blockIdx.x;               // (e, m)
    int e = bid >> 9, m = bid & 511;
    int cnt = g_cnt[e];
    int lim = (cnt + 63) & ~63;
    if (m >= lim) return;
    uint4* dst = (uint4*)(g_Ah + ((size_t)e * 512 + m) * 2048);   // 256 x 16B (8 halves)
    int tid = threadIdx.x;
    if (m < cnt) {
        int p = g_pairs[e][m];
        const float4* src = (const float4*)(x + (size_t)(p >> 1) * 2048) + tid * 2;
        float4 v0 = src[0], v1 = src[1];
        uint4 o;
        o.x = pack_h2(v0.x, v0.y); o.y = pack_h2(v0.z, v0.w);
        o.z = pack_h2(v1.x, v1.y); o.w = pack_h2(v1.z, v1.w);
        dst[tid] = o;
    } else {
        dst[tid] = make_uint4(0, 0, 0, 0);
    }
}

// ---------------- fp16 mma.sync GEMM -------------------------------------------
// BM=64, BN=128, BK=64; 256 threads; warps 2(m) x 4(n), warp tile 32x32.
// SMEM rows: 64 halves padded to 144B -> conflict-free ldmatrix.
// G1: B rows 0-63 = gate (w13 row n0+r), rows 64-127 = up (w13 row 1024+n0+r-64);
//     epilogue computes silu(gate)*up -> g_actE (fp16).
// G2: plain BN=128 tile of w2 -> g_yE (fp32).
#define A_STGB 9216                     // 64 rows * 144B
#define B_STGB 18432                    // 128 rows * 144B
#define SMEM_DYN (2 * A_STGB + 2 * B_STGB)   // 55296

template<int KTOT, bool G1>
__global__ void __launch_bounds__(256, 2) mma_gemm(
    const float* __restrict__ Ball,
    const float* __restrict__ Sall)
{
    constexpr int KS = KTOT / 64;
    constexpr int KB = KTOT / 128;

    const int e   = blockIdx.z;
    const int cnt = g_cnt[e];
    const int m0  = blockIdx.y << 6;
    if (m0 >= cnt) return;
    const int n0  = G1 ? (blockIdx.x << 6) : (blockIdx.x << 7);

    const __half* Ah = (G1 ? g_Ah : g_actE) + ((size_t)e * 512 + m0) * KTOT;

    extern __shared__ float dsm[];
    const uint32_t sbase = smem_u32(dsm);

    const int tid  = threadIdx.x;
    const int lane = tid & 31, w = tid >> 5;
    const int warpM = (w & 1) << 5;     // 0 or 32
    const int warpN = (w >> 1) << 5;    // 0,32,64,96

    // loader geometry: 16B granules, 8 per 128B row chunk
    const int rowg  = tid >> 3;         // 0..31
    const int col16 = tid & 7;
    const uint32_t ldoff = (uint32_t)(rowg * 144 + col16 * 16);

    // B source pointers per granule (4 granules -> 128 rows)
    const float* Bp[4];
#pragma unroll
    for (int i = 0; i < 4; i++) {
        int n = G1 ? ((i < 2) ? (n0 + rowg + 32 * i) : (1024 + n0 + rowg + 32 * (i - 2)))
                   : (n0 + rowg + 32 * i);
        Bp[i] = Ball + ((size_t)e * 2048 + n) * KTOT + col16 * 8;
    }
    const float* Sg = Sall + ((size_t)e * 16 + (n0 >> 7)) * KB;
    const float* Su = G1 ? (Sall + ((size_t)e * 16 + 8 + (n0 >> 7)) * KB) : Sg;

    // ldmatrix per-lane address bases
    const int l2 = lane & 15;
    const uint32_t aFragBase = (uint32_t)((warpM + (lane & 7) + ((lane >> 3) & 1) * 8) * 144
                                          + ((lane >> 4) & 1) * 16);
    const uint32_t bFragBase = (uint32_t)((warpN + (l2 & 7)) * 144 + ((l2 >> 3) & 1) * 16);

    float acc[2][4][4];
#pragma unroll
    for (int mt = 0; mt < 2; mt++)
#pragma unroll
        for (int nt = 0; nt < 4; nt++)
#pragma unroll
            for (int i = 0; i < 4; i++) acc[mt][nt][i] = 0.f;

    // -------- prologue: fill stage 0 --------
    {
#pragma unroll
        for (int i = 0; i < 2; i++)
            cpa16(sbase + ldoff + (uint32_t)(i * 4608),
                  Ah + (size_t)(rowg + 32 * i) * KTOT + col16 * 8);
        CP_COMMIT();
#pragma unroll
        for (int i = 0; i < 4; i++) {
            float sc = (G1 && i >= 2) ? Su[0] : Sg[0];
            float4 u = *(const float4*)(Bp[i]);
            float4 v = *(const float4*)(Bp[i] + 4);
            sts128(sbase + 2 * A_STGB + ldoff + (uint32_t)(i * 4608),
                   pack_h2(u.x * sc, u.y * sc), pack_h2(u.z * sc, u.w * sc),
                   pack_h2(v.x * sc, v.y * sc), pack_h2(v.z * sc, v.w * sc));
        }
        CP_WAIT0();
        __syncthreads();
    }

    // -------- main loop --------
    for (int ks = 0; ks < KS; ks++) {
        const int cur = ks & 1, nxt = cur ^ 1;
        const uint32_t aCur = sbase + (uint32_t)(cur * A_STGB);
        const uint32_t bCur = sbase + (uint32_t)(2 * A_STGB + cur * B_STGB);

        float4 bu[4], bv[4];
        float  sc[4];
        const bool more = (ks + 1 < KS);
        if (more) {
            const int kf = (ks + 1) * 64;
            const int kb = (ks + 1) >> 1;
            const uint32_t aNxt = sbase + (uint32_t)(nxt * A_STGB);
#pragma unroll
            for (int i = 0; i < 2; i++)
                cpa16(aNxt + ldoff + (uint32_t)(i * 4608),
                      Ah + (size_t)(rowg + 32 * i) * KTOT + kf + col16 * 8);
            CP_COMMIT();
#pragma unroll
            for (int i = 0; i < 4; i++) {
                bu[i] = *(const float4*)(Bp[i] + kf);
                bv[i] = *(const float4*)(Bp[i] + kf + 4);
                sc[i] = (G1 && i >= 2) ? Su[kb] : Sg[kb];
            }
        }

        // compute on cur: 4 k16 steps
#pragma unroll
        for (int s = 0; s < 4; s++) {
            uint32_t af[2][4], bf[4][2];
#pragma unroll
            for (int mt = 0; mt < 2; mt++)
                ldsm4(af[mt][0], af[mt][1], af[mt][2], af[mt][3],
                      aCur + aFragBase + (uint32_t)(mt * 16 * 144 + s * 32));
#pragma unroll
            for (int nt = 0; nt < 4; nt++)
                ldsm2(bf[nt][0], bf[nt][1],
                      bCur + bFragBase + (uint32_t)(nt * 8 * 144 + s * 32));
#pragma unroll
            for (int mt = 0; mt < 2; mt++)
#pragma unroll
                for (int nt = 0; nt < 4; nt++)
                    mma16(acc[mt][nt], af[mt], bf[nt]);
        }

        if (more) {
            const uint32_t bNxt = sbase + (uint32_t)(2 * A_STGB + nxt * B_STGB);
#pragma unroll
            for (int i = 0; i < 4; i++) {
                sts128(bNxt + ldoff + (uint32_t)(i * 4608),
                       pack_h2(bu[i].x * sc[i], bu[i].y * sc[i]),
                       pack_h2(bu[i].z * sc[i], bu[i].w * sc[i]),
                       pack_h2(bv[i].x * sc[i], bv[i].y * sc[i]),
                       pack_h2(bv[i].z * sc[i], bv[i].w * sc[i]));
            }
            CP_WAIT0();
        }
        __syncthreads();
    }

    // -------- epilogue --------
    const int rr = lane >> 2, cc = (lane & 3) << 1;
    if (!G1) {
        float* Cb = g_yE + ((size_t)e * 512 + m0) * 2048 + n0;
#pragma unroll
        for (int mt = 0; mt < 2; mt++)
#pragma unroll
            for (int nt = 0; nt < 4; nt++) {
                float* p0 = Cb + (size_t)(warpM + mt * 16 + rr) * 2048 + warpN + nt * 8 + cc;
                *(float2*)p0 = make_float2(acc[mt][nt][0], acc[mt][nt][1]);
                *(float2*)(p0 + 8 * 2048) = make_float2(acc[mt][nt][2], acc[mt][nt][3]);
            }
    } else {
        // fused silu(gate)*up. up warps (w>=4) stage accs through smem.
        float* ups = dsm;                           // 64 x 68 floats
        if (w >= 4) {
            const int wn = warpN - 64;
#pragma unroll
            for (int mt = 0; mt < 2; mt++)
#pragma unroll
                for (int nt = 0; nt < 4; nt++) {
                    int row = warpM + mt * 16 + rr;
                    int col = wn + nt * 8 + cc;
                    *(float2*)(ups + row * 68 + col)       = make_float2(acc[mt][nt][0], acc[mt][nt][1]);
                    *(float2*)(ups + (row + 8) * 68 + col) = make_float2(acc[mt][nt][2], acc[mt][nt][3]);
                }
        }
        __syncthreads();
        if (w < 4) {
            __half* act = g_actE + ((size_t)e * 512 + m0) * 1024 + n0;
#pragma unroll
            for (int mt = 0; mt < 2; mt++)
#pragma unroll
                for (int nt = 0; nt < 4; nt++) {
                    int row = warpM + mt * 16 + rr;
                    int col = warpN + nt * 8 + cc;
                    float2 u0 = *(float2*)(ups + row * 68 + col);
                    float2 u1 = *(float2*)(ups + (row + 8) * 68 + col);
                    float g0 = acc[mt][nt][0], g1 = acc[mt][nt][1];
                    float g2 = acc[mt][nt][2], g3 = acc[mt][nt][3];
                    float a0 = g0 / (1.f + __expf(-g0)) * u0.x;
                    float a1 = g1 / (1.f + __expf(-g1)) * u0.y;
                    float a2 = g2 / (1.f + __expf(-g2)) * u1.x;
                    float a3 = g3 / (1.f + __expf(-g3)) * u1.y;
                    *(uint32_t*)(act + (size_t)row * 1024 + col)       = pack_h2(a0, a1);
                    *(uint32_t*)(act + (size_t)(row + 8) * 1024 + col) = pack_h2(a2, a3);
                }
        }
    }
}

// ---------------- combine -------------------------------------------------------
__global__ void combine_kernel(const float* __restrict__ tw,
                               float* __restrict__ out) {
    int idx = blockIdx.x * 256 + threadIdx.x;     // over 256*2048/4
    int t  = idx >> 9;
    int h4 = (idx & 511) << 2;
    float w0 = tw[2 * t + 0], w1 = tw[2 * t + 1];
    const float4* y0 = (const float4*)(g_yE + (size_t)g_pos[2 * t + 0] * 2048 + h4);
    const float4* y1 = (const float4*)(g_yE + (size_t)g_pos[2 * t + 1] * 2048 + h4);
    float4 a = *y0, b = *y1;
    *(float4*)(out + (size_t)t * 2048 + h4) = make_float4(
        w0 * a.x + w1 * b.x, w0 * a.y + w1 * b.y,
        w0 * a.z + w1 * b.z, w0 * a.w + w1 * b.w);
}

// ---------------- entry ---------------------------------------------------------
extern "C" void kernel_launch(void* const* d_in, const int* in_sizes, int n_in,
                              void* d_out, int out_size) {
    const float* x   = (const float*)d_in[0];
    const int*   ids = (const int*)d_in[1];
    const float* tw  = (const float*)d_in[2];
    const float* w13 = (const float*)d_in[3];
    const float* s13 = (const float*)d_in[4];
    const float* w2  = (const float*)d_in[5];
    const float* s2  = (const float*)d_in[6];
    float* out = (float*)d_out;

    cudaFuncSetAttribute(mma_gemm<2048, true>,  cudaFuncAttributeMaxDynamicSharedMemorySize, SMEM_DYN);
    cudaFuncSetAttribute(mma_gemm<1024, false>, cudaFuncAttributeMaxDynamicSharedMemorySize, SMEM_DYN);

    route_kernel<<<1, NPAIRS>>>(ids);
    gather_kernel<<<NEXP * 512, 256>>>(x);

    dim3 grid(16, 8, NEXP);
    mma_gemm<2048, true><<<grid, 256, SMEM_DYN>>>(w13, s13);   // gate_up + silu fused
    mma_gemm<1024, false><<<grid, 256, SMEM_DYN>>>(w2, s2);    // down proj

    combine_kernel<<<(NTOK * 2048 / 4) / 256, 256>>>(tw, out);
}